// round 13
// baseline (speedup 1.0000x reference)
#include <cuda_runtime.h>
#include <cstdint>
#include <cstddef>

// ---------------- problem constants (fixed-shape problem) ----------------
#define Hc   128
#define NUc  200000
#define NMc  80000
#define Ec   2000000
#define ELc  500000
#define FDc  512

#define NMH  (NMc * Hc)            // 10,240,000 floats
#define NUH  ((size_t)NUc * Hc)    // 25,600,000 floats

// ---------------- static scratch (no allocations allowed) ----------------
// float buffer layout (in floats)
#define OFF_MOVIE_X ((size_t)0)                       // [NM][128]
#define OFF_HM      (OFF_MOVIE_X + NMH)               // [NM][256]: mmean | movie_h
#define OFF_MO      (OFF_HM + (size_t)2 * NMH)        // [NM][256]: movie_o | movie_o2
#define OFF_T1T2    (OFF_MO + (size_t)2 * NMH)        // [NM][256] fp32: t1 | t2
#define OFF_UH      (OFF_T1T2 + (size_t)2 * NMH)      // [NU][128] dense: user_h
#define OFF_UB      (OFF_UH + NUH)                    // [NU][128] dense: ub
#define OFF_GATEM   (OFF_UB + NUH)
#define OFF_C1      (OFF_GATEM + NMc)
#define OFF_V1      (OFF_C1 + 128)
#define OFF_WT      (OFF_V1 + 128)                    // Wr2_mu^T  [128][128]
#define OFF_WCAT    (OFF_WT + Hc * Hc)                // [256][128]: Wl2_um ; Wr2_um
#define BUF_TOTAL   (OFF_WCAT + 2 * Hc * Hc)

__device__ float g_buf[BUF_TOTAL];
__device__ int   g_deg[NUc + NMc];

// int scratch: CSR structures
#define IOFF_CSRU   ((size_t)0)                 // E
#define IOFF_CSRM   (IOFF_CSRU + Ec)            // E
#define IOFF_STARTU (IOFF_CSRM + Ec)            // NU+1
#define IOFF_STARTM (IOFF_STARTU + NUc + 1)     // NM+1
#define IOFF_CURSU  (IOFF_STARTM + NMc + 1)     // NU
#define IOFF_CURSM  (IOFF_CURSU + NUc)          // NM
#define IOFF_INCL   (IOFF_CURSM + NMc)          // max(NU,NM)
#define IOFF_BSUM   (IOFF_INCL + NUc)           // 256
#define IBUF_TOTAL  (IOFF_BSUM + 256)

__device__ int g_ibuf[IBUF_TOTAL];

typedef unsigned long long ull;

// ---------------- f32x2 packed-FMA helpers (Blackwell sm_100+) ----------------
__device__ __forceinline__ ull pk2(float lo, float hi) {
    ull r;
    asm("mov.b64 %0, {%1, %2};" : "=l"(r) : "f"(lo), "f"(hi));
    return r;
}
__device__ __forceinline__ void upk2(float& lo, float& hi, ull v) {
    asm("mov.b64 {%0, %1}, %2;" : "=f"(lo), "=f"(hi) : "l"(v));
}
__device__ __forceinline__ void ffma2(ull& d, ull a, ull b) {
    asm("fma.rn.f32x2 %0, %1, %2, %0;" : "+l"(d) : "l"(a), "l"(b));
}

// ---------------- degree counting ----------------
__global__ void k_deg(const int* __restrict__ src, const int* __restrict__ dst, int E) {
    int e = blockIdx.x * blockDim.x + threadIdx.x;
    if (e < E) {
        atomicAdd(&g_deg[src[e]], 1);
        atomicAdd(&g_deg[NUc + dst[e]], 1);
    }
}

// ---------------- scan: phase 1 ----------------
__global__ __launch_bounds__(1024) void k_scan1(const int* __restrict__ deg,
                                                int* __restrict__ incl,
                                                int* __restrict__ bsum, int N) {
    __shared__ int sm[1024];
    int t = threadIdx.x;
    int i = blockIdx.x * 1024 + t;
    int v = (i < N) ? deg[i] : 0;
    sm[t] = v;
    __syncthreads();
#pragma unroll
    for (int o = 1; o < 1024; o <<= 1) {
        int x = (t >= o) ? sm[t - o] : 0;
        __syncthreads();
        sm[t] += x;
        __syncthreads();
    }
    if (i < N) incl[i] = sm[t];
    if (t == 1023) bsum[blockIdx.x] = sm[1023];
}

// ---------------- scan: phase 2 ----------------
__global__ void k_scan2(int* __restrict__ bsum, int nb) {
    __shared__ int sm[256];
    int t = threadIdx.x;
    int v = (t < nb) ? bsum[t] : 0;
    sm[t] = v;
    __syncthreads();
#pragma unroll
    for (int o = 1; o < 256; o <<= 1) {
        int x = (t >= o) ? sm[t - o] : 0;
        __syncthreads();
        sm[t] += x;
        __syncthreads();
    }
    if (t < nb) bsum[t] = sm[t] - v;   // exclusive
}

// ---------------- scan: phase 3 ----------------
__global__ void k_scan3(const int* __restrict__ deg, const int* __restrict__ incl,
                        const int* __restrict__ bsum,
                        int* __restrict__ start, int* __restrict__ curs,
                        float* __restrict__ gate, int N) {
    int i = blockIdx.x * blockDim.x + threadIdx.x;
    if (i >= N) return;
    int d = deg[i];
    int s = incl[i] - d + bsum[i >> 10];
    start[i] = s;
    curs[i]  = s;
    if (i == N - 1) start[N] = s + d;
    if (gate) gate[i] = d > 0 ? 1.0f : 0.0f;
}

// ---------------- edge scatter into both CSRs ----------------
__global__ void k_scatter(const int* __restrict__ src, const int* __restrict__ dst,
                          int* __restrict__ cursU, int* __restrict__ cursM,
                          int* __restrict__ csrU, int* __restrict__ csrM, int E) {
    int e = blockIdx.x * blockDim.x + threadIdx.x;
    if (e >= E) return;
    int u = src[e], m = dst[e];
    csrU[atomicAdd(cursU + u, 1)] = m;
    csrM[atomicAdd(cursM + m, 1)] = u;
}

// ---------------- collapsed user_init terms ----------------
__global__ void k_vec(const float* __restrict__ u0, const float* __restrict__ Wl1_um,
                      const float* __restrict__ Wr1_mu, const float* __restrict__ bl1_mu,
                      float* __restrict__ c1, float* __restrict__ v1) {
    int n = threadIdx.x;
    float c = 0.0f, v = 0.0f;
    for (int k = 0; k < Hc; k++) {
        float uk = u0[k];
        c += uk * Wl1_um[k * Hc + n];
        v += uk * Wr1_mu[k * Hc + n];
    }
    c1[n] = c;
    v1[n] = bl1_mu[n] + v;
}

// ---------------- 128x128 transpose (for Wr2_mu^T) ----------------
__global__ void k_transp(const float* __restrict__ in, float* __restrict__ outw) {
    __shared__ float tile[32][33];
    int bx = blockIdx.x & 3, by = blockIdx.x >> 2;
    int x = bx * 32 + threadIdx.x, y = by * 32 + threadIdx.y;
    tile[threadIdx.y][threadIdx.x] = in[y * Hc + x];
    __syncthreads();
    outw[(bx * 32 + threadIdx.y) * Hc + by * 32 + threadIdx.x] = tile[threadIdx.x][threadIdx.y];
}

// ---------------- GEMM core: double-buffered smem, f32x2 FMAs ----------------
// C[M,128] = epilogue(A[M,K] @ W[K,128]); A row stride = lda.
// epilogue: t = acc + bias[n] + gate[row]*gvec[n]; optional relu; fp32 out, stride ldc.
__device__ __forceinline__ void gemm_core(
    const float* __restrict__ A, int lda, const float* __restrict__ W,
    float* __restrict__ C, int M, int K, int ldc,
    const float* __restrict__ bias,
    const float* __restrict__ gate, const float* __restrict__ gvec,
    int do_relu)
{
    __shared__ float As[2][16][128];   // [buf][k][m]
    __shared__ float Ws[2][16][128];   // [buf][k][n]

    int tid = threadIdx.x;
    int tx = tid & 15;         // output cols tx*8 .. tx*8+7
    int ty = tid >> 4;         // output rows ty*8 .. ty*8+7
    int brow = blockIdx.x * 128;

    ull acc2[4][8];
#pragma unroll
    for (int i = 0; i < 4; i++)
#pragma unroll
        for (int j = 0; j < 8; j++) acc2[i][j] = 0ull;

    float4 a_st[2], w_st[2];

    auto ldg_tiles = [&](int k0) {
#pragma unroll
        for (int it = 0; it < 2; it++) {
            int s = it * 256 + tid;
            int m = s >> 2;
            int k4 = (s & 3) << 2;
            int row = brow + m;
            a_st[it] = (row < M)
                ? *reinterpret_cast<const float4*>(A + (size_t)row * lda + k0 + k4)
                : make_float4(0.f, 0.f, 0.f, 0.f);
            int kw = s >> 5;
            int n4 = (s & 31) << 2;
            w_st[it] = *reinterpret_cast<const float4*>(W + (size_t)(k0 + kw) * Hc + n4);
        }
    };
    auto sts_tiles = [&](int b) {
#pragma unroll
        for (int it = 0; it < 2; it++) {
            int s = it * 256 + tid;
            int m = s >> 2;
            int k4 = (s & 3) << 2;
            As[b][k4 + 0][m] = a_st[it].x;
            As[b][k4 + 1][m] = a_st[it].y;
            As[b][k4 + 2][m] = a_st[it].z;
            As[b][k4 + 3][m] = a_st[it].w;
            int kw = s >> 5;
            int n4 = (s & 31) << 2;
            *reinterpret_cast<float4*>(&Ws[b][kw][n4]) = w_st[it];
        }
    };

    ldg_tiles(0);
    sts_tiles(0);
    __syncthreads();

    int nt = K >> 4;
    for (int t = 0; t < nt; t++) {
        int cur = t & 1;
        if (t + 1 < nt) ldg_tiles((t + 1) << 4);

#pragma unroll
        for (int kk = 0; kk < 16; kk++) {
            ulonglong2 av0 = *reinterpret_cast<const ulonglong2*>(&As[cur][kk][ty * 8]);
            ulonglong2 av1 = *reinterpret_cast<const ulonglong2*>(&As[cur][kk][ty * 8 + 4]);
            ull ap[4] = {av0.x, av0.y, av1.x, av1.y};

            float4 b0 = *reinterpret_cast<const float4*>(&Ws[cur][kk][tx * 8]);
            float4 b1 = *reinterpret_cast<const float4*>(&Ws[cur][kk][tx * 8 + 4]);
            ull bd[8] = {pk2(b0.x, b0.x), pk2(b0.y, b0.y), pk2(b0.z, b0.z), pk2(b0.w, b0.w),
                         pk2(b1.x, b1.x), pk2(b1.y, b1.y), pk2(b1.z, b1.z), pk2(b1.w, b1.w)};

#pragma unroll
            for (int ip = 0; ip < 4; ip++)
#pragma unroll
                for (int j = 0; j < 8; j++)
                    ffma2(acc2[ip][j], ap[ip], bd[j]);
        }

        if (t + 1 < nt) sts_tiles(cur ^ 1);
        __syncthreads();
    }

    float acc[8][8];
#pragma unroll
    for (int ip = 0; ip < 4; ip++)
#pragma unroll
        for (int j = 0; j < 8; j++)
            upk2(acc[2 * ip][j], acc[2 * ip + 1][j], acc2[ip][j]);

    // epilogue
#pragma unroll
    for (int i = 0; i < 8; i++) {
        int row = brow + ty * 8 + i;
        if (row >= M) continue;
        float g_ = gate ? gate[row] : 0.0f;
#pragma unroll
        for (int jj = 0; jj < 2; jj++) {
            int nb = tx * 8 + jj * 4;
            float v[4];
#pragma unroll
            for (int j = 0; j < 4; j++) {
                int n = nb + j;
                float t = acc[i][jj * 4 + j];
                if (bias) t += bias[n];
                if (gvec) t += g_ * gvec[n];
                if (do_relu) t = fmaxf(t, 0.0f);
                v[j] = t;
            }
            *reinterpret_cast<float4*>(C + (size_t)row * ldc + nb) =
                make_float4(v[0], v[1], v[2], v[3]);
        }
    }
}

__global__ __launch_bounds__(256, 2) void k_gemm(
    const float* __restrict__ A, int lda, const float* __restrict__ W,
    float* __restrict__ C, int M, int K, int ldc,
    const float* __restrict__ bias,
    const float* __restrict__ gate, const float* __restrict__ gvec, int do_relu)
{
    gemm_core(A, lda, W, C, M, K, ldc, bias, gate, gvec, do_relu);
}

// two GEMMs sharing the same A, selected by blockIdx.y
__global__ __launch_bounds__(256, 2) void k_gemm_dual(
    const float* __restrict__ A, int lda, int M, int K,
    const float* __restrict__ W0, float* __restrict__ C0, int ldc0,
    const float* __restrict__ bias0, const float* __restrict__ gate0,
    const float* __restrict__ gvec0, int relu0,
    const float* __restrict__ W1, float* __restrict__ C1, int ldc1,
    const float* __restrict__ bias1, const float* __restrict__ gate1,
    const float* __restrict__ gvec1, int relu1)
{
    bool sec = (blockIdx.y != 0);
    gemm_core(A, lda,
              sec ? W1 : W0, sec ? C1 : C0, M, K,
              sec ? ldc1 : ldc0,
              sec ? bias1 : bias0,
              sec ? gate1 : gate0, sec ? gvec1 : gvec0,
              sec ? relu1 : relu0);
}

// ---------------- fused user aggregation over CSR (fp32 t1|t2 interleaved table) -------
// uh[u] = relu( inv * sum t1[m] + v1 )   -> dense [NU][128]
// ub[u] = inv * sum t2[m] + bl2_mu       -> dense [NU][128]
__global__ void k_agg_user(const float4* __restrict__ t1t2, const int* __restrict__ csr,
                           const int* __restrict__ start, const float* __restrict__ v1,
                           const float* __restrict__ bl2,
                           float4* __restrict__ uh, float4* __restrict__ ub) {
    int u = blockIdx.x * (blockDim.x >> 5) + (threadIdx.x >> 5);
    if (u >= NUc) return;
    int lane = threadIdx.x & 31;
    int s = start[u], e = start[u + 1];

    float4 a1 = make_float4(0.f, 0.f, 0.f, 0.f);
    float4 a2 = make_float4(0.f, 0.f, 0.f, 0.f);
    int j = s;
    for (; j + 1 < e; j += 2) {
        int m0 = __ldg(csr + j);
        int m1 = __ldg(csr + j + 1);
        const float4* r0 = t1t2 + (size_t)m0 * 64;
        const float4* r1 = t1t2 + (size_t)m1 * 64;
        float4 x0 = __ldg(r0 + lane);
        float4 y0 = __ldg(r0 + 32 + lane);
        float4 x1 = __ldg(r1 + lane);
        float4 y1 = __ldg(r1 + 32 + lane);
        a1.x += x0.x + x1.x; a1.y += x0.y + x1.y; a1.z += x0.z + x1.z; a1.w += x0.w + x1.w;
        a2.x += y0.x + y1.x; a2.y += y0.y + y1.y; a2.z += y0.z + y1.z; a2.w += y0.w + y1.w;
    }
    if (j < e) {
        int m0 = __ldg(csr + j);
        const float4* r0 = t1t2 + (size_t)m0 * 64;
        float4 x0 = __ldg(r0 + lane);
        float4 y0 = __ldg(r0 + 32 + lane);
        a1.x += x0.x; a1.y += x0.y; a1.z += x0.z; a1.w += x0.w;
        a2.x += y0.x; a2.y += y0.y; a2.z += y0.z; a2.w += y0.w;
    }

    float inv = 1.0f / (float)max(e - s, 1);
    float4 vv = reinterpret_cast<const float4*>(v1)[lane];
    float4 bb = reinterpret_cast<const float4*>(bl2)[lane];
    float4 r;
    r.x = fmaxf(a1.x * inv + vv.x, 0.0f);
    r.y = fmaxf(a1.y * inv + vv.y, 0.0f);
    r.z = fmaxf(a1.z * inv + vv.z, 0.0f);
    r.w = fmaxf(a1.w * inv + vv.w, 0.0f);
    float4 m2;
    m2.x = a2.x * inv + bb.x;
    m2.y = a2.y * inv + bb.y;
    m2.z = a2.z * inv + bb.z;
    m2.w = a2.w * inv + bb.w;
    size_t o = (size_t)u * 32 + lane;   // dense 128-float rows
    uh[o] = r;
    ub[o] = m2;
}

// ---------------- movie aggregation: hm[m][0:128) = mean_u user_h[u] ----------------
// gathers from the DENSE uh table (best L2 locality), writes interleaved hm slot0
__global__ void k_agg_movie(const float4* __restrict__ uh, const int* __restrict__ csr,
                            const int* __restrict__ start, float4* __restrict__ hm) {
    int m = blockIdx.x * (blockDim.x >> 5) + (threadIdx.x >> 5);
    if (m >= NMc) return;
    int lane = threadIdx.x & 31;
    int s = start[m], e = start[m + 1];

    float4 a = make_float4(0.f, 0.f, 0.f, 0.f);
    int j = s;
    for (; j + 1 < e; j += 2) {
        int u0 = __ldg(csr + j);
        int u1 = __ldg(csr + j + 1);
        float4 x0 = __ldg(uh + (size_t)u0 * 32 + lane);
        float4 x1 = __ldg(uh + (size_t)u1 * 32 + lane);
        a.x += x0.x + x1.x; a.y += x0.y + x1.y; a.z += x0.z + x1.z; a.w += x0.w + x1.w;
    }
    if (j < e) {
        float4 x0 = __ldg(uh + (size_t)__ldg(csr + j) * 32 + lane);
        a.x += x0.x; a.y += x0.y; a.z += x0.z; a.w += x0.w;
    }
    float inv = 1.0f / (float)max(e - s, 1);
    a.x *= inv; a.y *= inv; a.z *= inv; a.w *= inv;
    hm[(size_t)m * 64 + lane] = a;   // mmean slot of interleaved [NM][256]
}

// ---------------- supervision-edge dot products (two-term) ----------------
// out[e] = user_h·movie_o2 + ub·movie_o   (mo interleaved [NM][256]: movie_o|movie_o2)
__global__ void k_dot2(const float4* __restrict__ uh, const float4* __restrict__ ub,
                       const float4* __restrict__ mo,
                       const int* __restrict__ lu, const int* __restrict__ lm,
                       float* __restrict__ out, int EL) {
    int e = (blockIdx.x * blockDim.x + threadIdx.x) >> 5;
    if (e >= EL) return;
    int lane = threadIdx.x & 31;
    size_t ou = (size_t)__ldg(lu + e) * 32 + lane;
    size_t om = (size_t)__ldg(lm + e) * 64 + lane;
    float4 a  = __ldg(uh + ou);        // user_h
    float4 a2 = __ldg(ub + ou);        // ub
    float4 b  = __ldg(mo + om);        // movie_o
    float4 b2 = __ldg(mo + om + 32);   // movie_o2
    float s = a.x * b2.x + a.y * b2.y + a.z * b2.z + a.w * b2.w
            + a2.x * b.x + a2.y * b.y + a2.z * b.z + a2.w * b.w;
#pragma unroll
    for (int o = 16; o; o >>= 1) s += __shfl_xor_sync(0xffffffffu, s, o);
    if (lane == 0) out[e] = s;
}

// ---------------- launcher ----------------
extern "C" void kernel_launch(void* const* d_in, const int* in_sizes, int n_in,
                              void* d_out, int out_size) {
    int wb = n_in - 14;  // weights are the last 14 inputs

    const float* movie_feats = (const float*)d_in[0];
    const float* user_init   = (const float*)d_in[1];
    const int*   edge_src    = (const int*)d_in[2];
    const int*   edge_dst    = (const int*)d_in[3];
    const int*   lbl_user    = (const int*)d_in[4];
    const int*   lbl_movie   = (const int*)d_in[5];

    const float* Wm     = (const float*)d_in[wb + 0];
    const float* bm     = (const float*)d_in[wb + 1];
    const float* Wl1_um = (const float*)d_in[wb + 2];
    const float* bl1_um = (const float*)d_in[wb + 3];
    const float* Wr1_um = (const float*)d_in[wb + 4];
    const float* Wl1_mu = (const float*)d_in[wb + 5];
    const float* bl1_mu = (const float*)d_in[wb + 6];
    const float* Wr1_mu = (const float*)d_in[wb + 7];
    const float* Wl2_um = (const float*)d_in[wb + 8];
    const float* bl2_um = (const float*)d_in[wb + 9];
    const float* Wr2_um = (const float*)d_in[wb + 10];
    const float* Wl2_mu = (const float*)d_in[wb + 11];
    const float* bl2_mu = (const float*)d_in[wb + 12];
    const float* Wr2_mu = (const float*)d_in[wb + 13];

    float* out = (float*)d_out;

    float* buf = nullptr;
    int*   deg = nullptr;
    int*   ibuf = nullptr;
    cudaGetSymbolAddress((void**)&buf, g_buf);
    cudaGetSymbolAddress((void**)&deg, g_deg);
    cudaGetSymbolAddress((void**)&ibuf, g_ibuf);

    float* movie_x = buf + OFF_MOVIE_X;
    float* hm      = buf + OFF_HM;        // [NM][256]: mmean | movie_h
    float* mo      = buf + OFF_MO;        // [NM][256]: movie_o | movie_o2
    float* t1t2    = buf + OFF_T1T2;      // [NM][256]: t1 | t2 (fp32)
    float* uh      = buf + OFF_UH;        // [NU][128] dense
    float* ub      = buf + OFF_UB;        // [NU][128] dense
    float* gateM   = buf + OFF_GATEM;
    float* c1      = buf + OFF_C1;
    float* v1      = buf + OFF_V1;
    float* WT      = buf + OFF_WT;
    float* Wcat    = buf + OFF_WCAT;      // [256][128]

    int* csrU   = ibuf + IOFF_CSRU;
    int* csrM   = ibuf + IOFF_CSRM;
    int* startU = ibuf + IOFF_STARTU;
    int* startM = ibuf + IOFF_STARTM;
    int* cursU  = ibuf + IOFF_CURSU;
    int* cursM  = ibuf + IOFF_CURSM;
    int* incl   = ibuf + IOFF_INCL;
    int* bsum   = ibuf + IOFF_BSUM;

    const int nbU = (NUc + 1023) / 1024;   // 196
    const int nbM = (NMc + 1023) / 1024;   // 79
    const int gemmM_blocks = NMc / 128;    // 625

    // -------- CSR build --------
    cudaMemsetAsync(deg, 0, sizeof(int) * (NUc + NMc));
    k_deg<<<(Ec + 255) / 256, 256>>>(edge_src, edge_dst, Ec);

    k_scan1<<<nbU, 1024>>>(deg, incl, bsum, NUc);
    k_scan2<<<1, 256>>>(bsum, nbU);
    k_scan3<<<nbU, 1024>>>(deg, incl, bsum, startU, cursU, nullptr, NUc);

    k_scan1<<<nbM, 1024>>>(deg + NUc, incl, bsum, NMc);
    k_scan2<<<1, 256>>>(bsum, nbM);
    k_scan3<<<nbM, 1024>>>(deg + NUc, incl, bsum, startM, cursM, gateM, NMc);

    k_scatter<<<(Ec + 255) / 256, 256>>>(edge_src, edge_dst, cursU, cursM, csrU, csrM, Ec);

    // collapsed user_init terms, Wr2_mu^T, stacked [Wl2_um ; Wr2_um]
    k_vec<<<1, 128>>>(user_init, Wl1_um, Wr1_mu, bl1_mu, c1, v1);
    k_transp<<<16, dim3(32, 32)>>>(Wr2_mu, WT);
    cudaMemcpyAsync(Wcat,           Wl2_um, Hc * Hc * sizeof(float), cudaMemcpyDeviceToDevice);
    cudaMemcpyAsync(Wcat + Hc * Hc, Wr2_um, Hc * Hc * sizeof(float), cudaMemcpyDeviceToDevice);

    // -------- GEMM chain (movie side) --------
    // movie_x = movie_feats @ Wm + bm   (K=512)
    k_gemm<<<gemmM_blocks, 256>>>(movie_feats, FDc, Wm, movie_x, NMc, FDc, Hc,
                                  bm, nullptr, nullptr, 0);
    // dual: t1 = movie_x@Wl1_mu (t1t2 slot0, ldc=256)
    //       movie_h = relu(movie_x@Wr1_um + bl1_um + gateM*c1) (hm slot1, ldc=256)
    k_gemm_dual<<<dim3(gemmM_blocks, 2), 256>>>(movie_x, Hc, NMc, Hc,
        Wl1_mu, t1t2,     256, nullptr, nullptr, nullptr, 0,
        Wr1_um, hm + 128, 256, bl1_um, gateM, c1, 1);
    // t2 = movie_h @ Wl2_mu   (A = hm slot1, lda=256; out t1t2 slot1)
    k_gemm<<<gemmM_blocks, 256>>>(hm + 128, 256, Wl2_mu, t1t2 + 128, NMc, Hc, 256,
                                  nullptr, nullptr, nullptr, 0);

    // -------- aggregations (CSR gather, no atomics, no memsets) --------
    k_agg_user<<<(NUc + 7) / 8, 256>>>((const float4*)t1t2, csrU, startU, v1, bl2_mu,
                                       (float4*)uh, (float4*)ub);
    k_agg_movie<<<(NMc + 7) / 8, 256>>>((const float4*)uh, csrM, startM, (float4*)hm);

    // -------- output GEMMs --------
    // movie_o = [mmean | movie_h] @ [Wl2_um ; Wr2_um] + bl2_um   (K=256)
    k_gemm<<<gemmM_blocks, 256>>>(hm, 256, Wcat, mo, NMc, 256, 256,
                                  bl2_um, nullptr, nullptr, 0);
    // movie_o2 = movie_o @ Wr2_mu^T   (A = mo slot0, lda=256; out mo slot1)
    k_gemm<<<gemmM_blocks, 256>>>(mo, 256, WT, mo + 128, NMc, Hc, 256,
                                  nullptr, nullptr, nullptr, 0);

    // out[e] = user_h·movie_o2 + ub·movie_o
    k_dot2<<<(ELc + 7) / 8, 256>>>((const float4*)uh, (const float4*)ub,
                                   (const float4*)mo, lbl_user, lbl_movie, out, ELc);
}

// round 15
// speedup vs baseline: 1.0689x; 1.0689x over previous
#include <cuda_runtime.h>
#include <cstdint>
#include <cstddef>

// ---------------- problem constants (fixed-shape problem) ----------------
#define Hc   128
#define NUc  200000
#define NMc  80000
#define Ec   2000000
#define ELc  500000
#define FDc  512

#define NMH  (NMc * Hc)            // 10,240,000 floats
#define NUH  ((size_t)NUc * Hc)    // 25,600,000 floats

// ---------------- static scratch (no allocations allowed) ----------------
#define OFF_MOVIE_X   ((size_t)0)
#define OFF_T1T2      (OFF_MOVIE_X + NMH)            // interleaved [NM][256]: t1 | t2
#define OFF_MOVIE_H   (OFF_T1T2 + (size_t)2 * NMH)
#define OFF_MOVIE_TMP (OFF_MOVIE_H + NMH)
#define OFF_MSUM      (OFF_MOVIE_TMP + NMH)
#define OFF_MOVIE_O   (OFF_MSUM + NMH)
#define OFF_MOVIE_O2  (OFF_MOVIE_O + NMH)
#define OFF_USER_H    (OFF_MOVIE_O2 + NMH)
#define OFF_UB        (OFF_USER_H + NUH)             // umean2 + bl2_mu
#define OFF_INVM      (OFF_UB + NUH)
#define OFF_GATEM     (OFF_INVM + NMc)
#define OFF_C1        (OFF_GATEM + NMc)
#define OFF_V1        (OFF_C1 + 128)
#define OFF_WT        (OFF_V1 + 128)                 // Wr2_mu^T, 128*128
#define BUF_TOTAL     (OFF_WT + Hc * Hc)

__device__ float g_buf[BUF_TOTAL];
__device__ int   g_deg[NUc + NMc];

// int scratch: CSR structures
#define IOFF_CSRU   ((size_t)0)                 // E
#define IOFF_CSRM   (IOFF_CSRU + Ec)            // E
#define IOFF_STARTU (IOFF_CSRM + Ec)            // NU+1
#define IOFF_STARTM (IOFF_STARTU + NUc + 1)     // NM+1
#define IOFF_CURSU  (IOFF_STARTM + NMc + 1)     // NU
#define IOFF_CURSM  (IOFF_CURSU + NUc)          // NM
#define IOFF_INCL   (IOFF_CURSM + NMc)          // max(NU,NM)
#define IOFF_BSUM   (IOFF_INCL + NUc)           // 256
#define IBUF_TOTAL  (IOFF_BSUM + 256)

__device__ int g_ibuf[IBUF_TOTAL];

typedef unsigned long long ull;

// ---------------- f32x2 packed-FMA helpers (Blackwell sm_100+) ----------------
__device__ __forceinline__ ull pk2(float lo, float hi) {
    ull r;
    asm("mov.b64 %0, {%1, %2};" : "=l"(r) : "f"(lo), "f"(hi));
    return r;
}
__device__ __forceinline__ void upk2(float& lo, float& hi, ull v) {
    asm("mov.b64 {%0, %1}, %2;" : "=f"(lo), "=f"(hi) : "l"(v));
}
__device__ __forceinline__ void ffma2(ull& d, ull a, ull b) {
    asm("fma.rn.f32x2 %0, %1, %2, %0;" : "+l"(d) : "l"(a), "l"(b));
}

// ---------------- degree counting ----------------
__global__ void k_deg(const int* __restrict__ src, const int* __restrict__ dst, int E) {
    int e = blockIdx.x * blockDim.x + threadIdx.x;
    if (e < E) {
        atomicAdd(&g_deg[src[e]], 1);
        atomicAdd(&g_deg[NUc + dst[e]], 1);
    }
}

// ---------------- scan: phase 1 ----------------
__global__ __launch_bounds__(1024) void k_scan1(const int* __restrict__ deg,
                                                int* __restrict__ incl,
                                                int* __restrict__ bsum, int N) {
    __shared__ int sm[1024];
    int t = threadIdx.x;
    int i = blockIdx.x * 1024 + t;
    int v = (i < N) ? deg[i] : 0;
    sm[t] = v;
    __syncthreads();
#pragma unroll
    for (int o = 1; o < 1024; o <<= 1) {
        int x = (t >= o) ? sm[t - o] : 0;
        __syncthreads();
        sm[t] += x;
        __syncthreads();
    }
    if (i < N) incl[i] = sm[t];
    if (t == 1023) bsum[blockIdx.x] = sm[1023];
}

// ---------------- scan: phase 2 ----------------
__global__ void k_scan2(int* __restrict__ bsum, int nb) {
    __shared__ int sm[256];
    int t = threadIdx.x;
    int v = (t < nb) ? bsum[t] : 0;
    sm[t] = v;
    __syncthreads();
#pragma unroll
    for (int o = 1; o < 256; o <<= 1) {
        int x = (t >= o) ? sm[t - o] : 0;
        __syncthreads();
        sm[t] += x;
        __syncthreads();
    }
    if (t < nb) bsum[t] = sm[t] - v;   // exclusive
}

// ---------------- scan: phase 3 ----------------
__global__ void k_scan3(const int* __restrict__ deg, const int* __restrict__ incl,
                        const int* __restrict__ bsum,
                        int* __restrict__ start, int* __restrict__ curs,
                        float* __restrict__ inv, float* __restrict__ gate, int N) {
    int i = blockIdx.x * blockDim.x + threadIdx.x;
    if (i >= N) return;
    int d = deg[i];
    int s = incl[i] - d + bsum[i >> 10];
    start[i] = s;
    curs[i]  = s;
    if (i == N - 1) start[N] = s + d;
    if (inv)  inv[i]  = 1.0f / (float)max(d, 1);
    if (gate) gate[i] = d > 0 ? 1.0f : 0.0f;
}

// ---------------- edge scatter into both CSRs ----------------
__global__ void k_scatter(const int* __restrict__ src, const int* __restrict__ dst,
                          int* __restrict__ cursU, int* __restrict__ cursM,
                          int* __restrict__ csrU, int* __restrict__ csrM, int E) {
    int e = blockIdx.x * blockDim.x + threadIdx.x;
    if (e >= E) return;
    int u = src[e], m = dst[e];
    csrU[atomicAdd(cursU + u, 1)] = m;
    csrM[atomicAdd(cursM + m, 1)] = u;
}

// ---------------- collapsed user_init terms ----------------
__global__ void k_vec(const float* __restrict__ u0, const float* __restrict__ Wl1_um,
                      const float* __restrict__ Wr1_mu, const float* __restrict__ bl1_mu,
                      float* __restrict__ c1, float* __restrict__ v1) {
    int n = threadIdx.x;
    float c = 0.0f, v = 0.0f;
    for (int k = 0; k < Hc; k++) {
        float uk = u0[k];
        c += uk * Wl1_um[k * Hc + n];
        v += uk * Wr1_mu[k * Hc + n];
    }
    c1[n] = c;
    v1[n] = bl1_mu[n] + v;
}

// ---------------- 128x128 transpose (for Wr2_mu^T) ----------------
__global__ void k_transp(const float* __restrict__ in, float* __restrict__ outw) {
    __shared__ float tile[32][33];
    int bx = blockIdx.x & 3, by = blockIdx.x >> 2;
    int x = bx * 32 + threadIdx.x, y = by * 32 + threadIdx.y;
    tile[threadIdx.y][threadIdx.x] = in[y * Hc + x];
    __syncthreads();
    outw[(bx * 32 + threadIdx.y) * Hc + by * 32 + threadIdx.x] = tile[threadIdx.x][threadIdx.y];
}

// ---------------- GEMM core: double-buffered smem, f32x2 FMAs ----------------
// C[M,128] = epilogue(A[M,K] @ W[K,128]); A row stride = K.
// epilogue: t = ascale[row]*acc + bias[n] + gate[row]*gvec[n] + Cadd[row,n]
__device__ __forceinline__ void gemm_core(
    const float* __restrict__ A, const float* __restrict__ W, float* __restrict__ C,
    int M, int K, int ldc,
    const float* __restrict__ bias,
    const float* __restrict__ ascale,
    const float* __restrict__ Cadd,
    const float* __restrict__ gate, const float* __restrict__ gvec,
    int do_relu)
{
    __shared__ float As[2][16][128];   // [buf][k][m]
    __shared__ float Ws[2][16][128];   // [buf][k][n]

    int tid = threadIdx.x;
    int tx = tid & 15;         // output cols tx*8 .. tx*8+7
    int ty = tid >> 4;         // output rows ty*8 .. ty*8+7
    int brow = blockIdx.x * 128;

    ull acc2[4][8];
#pragma unroll
    for (int i = 0; i < 4; i++)
#pragma unroll
        for (int j = 0; j < 8; j++) acc2[i][j] = 0ull;

    float4 a_st[2], w_st[2];

    auto ldg_tiles = [&](int k0) {
#pragma unroll
        for (int it = 0; it < 2; it++) {
            int s = it * 256 + tid;
            int m = s >> 2;
            int k4 = (s & 3) << 2;
            int row = brow + m;
            a_st[it] = (row < M)
                ? *reinterpret_cast<const float4*>(A + (size_t)row * K + k0 + k4)
                : make_float4(0.f, 0.f, 0.f, 0.f);
            int kw = s >> 5;
            int n4 = (s & 31) << 2;
            w_st[it] = *reinterpret_cast<const float4*>(W + (size_t)(k0 + kw) * Hc + n4);
        }
    };
    auto sts_tiles = [&](int b) {
#pragma unroll
        for (int it = 0; it < 2; it++) {
            int s = it * 256 + tid;
            int m = s >> 2;
            int k4 = (s & 3) << 2;
            As[b][k4 + 0][m] = a_st[it].x;
            As[b][k4 + 1][m] = a_st[it].y;
            As[b][k4 + 2][m] = a_st[it].z;
            As[b][k4 + 3][m] = a_st[it].w;
            int kw = s >> 5;
            int n4 = (s & 31) << 2;
            *reinterpret_cast<float4*>(&Ws[b][kw][n4]) = w_st[it];
        }
    };

    ldg_tiles(0);
    sts_tiles(0);
    __syncthreads();

    int nt = K >> 4;
    for (int t = 0; t < nt; t++) {
        int cur = t & 1;
        if (t + 1 < nt) ldg_tiles((t + 1) << 4);

#pragma unroll
        for (int kk = 0; kk < 16; kk++) {
            ulonglong2 av0 = *reinterpret_cast<const ulonglong2*>(&As[cur][kk][ty * 8]);
            ulonglong2 av1 = *reinterpret_cast<const ulonglong2*>(&As[cur][kk][ty * 8 + 4]);
            ull ap[4] = {av0.x, av0.y, av1.x, av1.y};

            float4 b0 = *reinterpret_cast<const float4*>(&Ws[cur][kk][tx * 8]);
            float4 b1 = *reinterpret_cast<const float4*>(&Ws[cur][kk][tx * 8 + 4]);
            ull bd[8] = {pk2(b0.x, b0.x), pk2(b0.y, b0.y), pk2(b0.z, b0.z), pk2(b0.w, b0.w),
                         pk2(b1.x, b1.x), pk2(b1.y, b1.y), pk2(b1.z, b1.z), pk2(b1.w, b1.w)};

#pragma unroll
            for (int ip = 0; ip < 4; ip++)
#pragma unroll
                for (int j = 0; j < 8; j++)
                    ffma2(acc2[ip][j], ap[ip], bd[j]);
        }

        if (t + 1 < nt) sts_tiles(cur ^ 1);
        __syncthreads();
    }

    float acc[8][8];
#pragma unroll
    for (int ip = 0; ip < 4; ip++)
#pragma unroll
        for (int j = 0; j < 8; j++)
            upk2(acc[2 * ip][j], acc[2 * ip + 1][j], acc2[ip][j]);

    // epilogue
#pragma unroll
    for (int i = 0; i < 8; i++) {
        int row = brow + ty * 8 + i;
        if (row >= M) continue;
        float as_ = ascale ? ascale[row] : 1.0f;
        float g_  = gate   ? gate[row]   : 0.0f;
#pragma unroll
        for (int jj = 0; jj < 2; jj++) {
            int nb = tx * 8 + jj * 4;
            float4 cadd = make_float4(0.f, 0.f, 0.f, 0.f);
            if (Cadd)
                cadd = *reinterpret_cast<const float4*>(Cadd + (size_t)row * Hc + nb);
            float ca[4] = {cadd.x, cadd.y, cadd.z, cadd.w};
            float4 v;
            float* vp = &v.x;
#pragma unroll
            for (int j = 0; j < 4; j++) {
                int n = nb + j;
                float tacc = acc[i][jj * 4 + j] * as_;
                if (bias) tacc += bias[n];
                if (gvec) tacc += g_ * gvec[n];
                if (Cadd) tacc += ca[j];
                if (do_relu) tacc = fmaxf(tacc, 0.0f);
                vp[j] = tacc;
            }
            *reinterpret_cast<float4*>(C + (size_t)row * ldc + nb) = v;
        }
    }
}

__global__ __launch_bounds__(256, 2) void k_gemm(
    const float* __restrict__ A, const float* __restrict__ W, float* __restrict__ C,
    int M, int K, int ldc,
    const float* __restrict__ bias, const float* __restrict__ ascale,
    const float* __restrict__ Cadd,
    const float* __restrict__ gate, const float* __restrict__ gvec, int do_relu)
{
    gemm_core(A, W, C, M, K, ldc, bias, ascale, Cadd, gate, gvec, do_relu);
}

// two GEMMs sharing the same A, selected by blockIdx.y (merged launch -> one tail wave)
__global__ __launch_bounds__(256, 2) void k_gemm_dual(
    const float* __restrict__ A, int M, int K,
    const float* __restrict__ W0, float* __restrict__ C0, int ldc0,
    const float* __restrict__ bias0, const float* __restrict__ gate0,
    const float* __restrict__ gvec0, int relu0,
    const float* __restrict__ W1, float* __restrict__ C1, int ldc1,
    const float* __restrict__ bias1, const float* __restrict__ gate1,
    const float* __restrict__ gvec1, int relu1)
{
    bool sec = (blockIdx.y != 0);
    gemm_core(A,
              sec ? W1 : W0, sec ? C1 : C0, M, K, sec ? ldc1 : ldc0,
              sec ? bias1 : bias0, nullptr, nullptr,
              sec ? gate1 : gate0, sec ? gvec1 : gvec0,
              sec ? relu1 : relu0);
}

// ---------------- fused user aggregation over CSR (t1+t2 interleaved table) ----------------
// uh[u] = relu( inv * sum_m t1[m] + v1 ),  inv = 1/max(deg,1)
// ub[u] = inv * sum_m t2[m] + bl2_mu
__global__ void k_agg_user(const float4* __restrict__ t1t2, const int* __restrict__ csr,
                           const int* __restrict__ start, const float* __restrict__ v1,
                           const float* __restrict__ bl2,
                           float4* __restrict__ uh, float4* __restrict__ ub) {
    int u = blockIdx.x * (blockDim.x >> 5) + (threadIdx.x >> 5);
    if (u >= NUc) return;
    int lane = threadIdx.x & 31;
    int s = start[u], e = start[u + 1];

    float4 a1 = make_float4(0.f, 0.f, 0.f, 0.f);
    float4 a2 = make_float4(0.f, 0.f, 0.f, 0.f);
    int j = s;
    for (; j + 1 < e; j += 2) {
        int m0 = __ldg(csr + j);
        int m1 = __ldg(csr + j + 1);
        const float4* r0 = t1t2 + (size_t)m0 * 64;
        const float4* r1 = t1t2 + (size_t)m1 * 64;
        float4 x0 = __ldg(r0 + lane);
        float4 y0 = __ldg(r0 + 32 + lane);
        float4 x1 = __ldg(r1 + lane);
        float4 y1 = __ldg(r1 + 32 + lane);
        a1.x += x0.x + x1.x; a1.y += x0.y + x1.y; a1.z += x0.z + x1.z; a1.w += x0.w + x1.w;
        a2.x += y0.x + y1.x; a2.y += y0.y + y1.y; a2.z += y0.z + y1.z; a2.w += y0.w + y1.w;
    }
    if (j < e) {
        int m0 = __ldg(csr + j);
        const float4* r0 = t1t2 + (size_t)m0 * 64;
        float4 x0 = __ldg(r0 + lane);
        float4 y0 = __ldg(r0 + 32 + lane);
        a1.x += x0.x; a1.y += x0.y; a1.z += x0.z; a1.w += x0.w;
        a2.x += y0.x; a2.y += y0.y; a2.z += y0.z; a2.w += y0.w;
    }

    float inv = 1.0f / (float)max(e - s, 1);
    float4 vv = reinterpret_cast<const float4*>(v1)[lane];
    float4 bb = reinterpret_cast<const float4*>(bl2)[lane];
    float4 r;
    r.x = fmaxf(a1.x * inv + vv.x, 0.0f);
    r.y = fmaxf(a1.y * inv + vv.y, 0.0f);
    r.z = fmaxf(a1.z * inv + vv.z, 0.0f);
    r.w = fmaxf(a1.w * inv + vv.w, 0.0f);
    float4 m2;
    m2.x = a2.x * inv + bb.x;
    m2.y = a2.y * inv + bb.y;
    m2.z = a2.z * inv + bb.z;
    m2.w = a2.w * inv + bb.w;
    size_t o = (size_t)u * 32 + lane;
    uh[o] = r;
    ub[o] = m2;
}

// ---------------- movie aggregation over CSR: msum[m] = sum_u user_h[u] ----------------
__global__ void k_agg_movie(const float4* __restrict__ uh, const int* __restrict__ csr,
                            const int* __restrict__ start, float4* __restrict__ msum) {
    int m = blockIdx.x * (blockDim.x >> 5) + (threadIdx.x >> 5);
    if (m >= NMc) return;
    int lane = threadIdx.x & 31;
    int s = start[m], e = start[m + 1];

    float4 a = make_float4(0.f, 0.f, 0.f, 0.f);
    int j = s;
    for (; j + 1 < e; j += 2) {
        int u0 = __ldg(csr + j);
        int u1 = __ldg(csr + j + 1);
        float4 x0 = __ldg(uh + (size_t)u0 * 32 + lane);
        float4 x1 = __ldg(uh + (size_t)u1 * 32 + lane);
        a.x += x0.x + x1.x; a.y += x0.y + x1.y; a.z += x0.z + x1.z; a.w += x0.w + x1.w;
    }
    if (j < e) {
        float4 x0 = __ldg(uh + (size_t)__ldg(csr + j) * 32 + lane);
        a.x += x0.x; a.y += x0.y; a.z += x0.z; a.w += x0.w;
    }
    msum[(size_t)m * 32 + lane] = a;
}

// ---------------- supervision-edge dot products (two-term) ----------------
// out[e] = uh[u]·mo2[m] + ub[u]·mo[m]
__global__ void k_dot2(const float4* __restrict__ uh, const float4* __restrict__ ub,
                       const float4* __restrict__ mo, const float4* __restrict__ mo2,
                       const int* __restrict__ lu, const int* __restrict__ lm,
                       float* __restrict__ out, int EL) {
    int e = (blockIdx.x * blockDim.x + threadIdx.x) >> 5;
    if (e >= EL) return;
    int lane = threadIdx.x & 31;
    size_t ou = (size_t)__ldg(lu + e) * 32 + lane;
    size_t om = (size_t)__ldg(lm + e) * 32 + lane;
    float4 a  = __ldg(uh + ou);
    float4 a2 = __ldg(ub + ou);
    float4 b2 = __ldg(mo2 + om);
    float4 b  = __ldg(mo + om);
    float s = a.x * b2.x + a.y * b2.y + a.z * b2.z + a.w * b2.w
            + a2.x * b.x + a2.y * b.y + a2.z * b.z + a2.w * b.w;
#pragma unroll
    for (int o = 16; o; o >>= 1) s += __shfl_xor_sync(0xffffffffu, s, o);
    if (lane == 0) out[e] = s;
}

// ---------------- launcher ----------------
extern "C" void kernel_launch(void* const* d_in, const int* in_sizes, int n_in,
                              void* d_out, int out_size) {
    int wb = n_in - 14;  // weights are the last 14 inputs

    const float* movie_feats = (const float*)d_in[0];
    const float* user_init   = (const float*)d_in[1];
    const int*   edge_src    = (const int*)d_in[2];
    const int*   edge_dst    = (const int*)d_in[3];
    const int*   lbl_user    = (const int*)d_in[4];
    const int*   lbl_movie   = (const int*)d_in[5];

    const float* Wm     = (const float*)d_in[wb + 0];
    const float* bm     = (const float*)d_in[wb + 1];
    const float* Wl1_um = (const float*)d_in[wb + 2];
    const float* bl1_um = (const float*)d_in[wb + 3];
    const float* Wr1_um = (const float*)d_in[wb + 4];
    const float* Wl1_mu = (const float*)d_in[wb + 5];
    const float* bl1_mu = (const float*)d_in[wb + 6];
    const float* Wr1_mu = (const float*)d_in[wb + 7];
    const float* Wl2_um = (const float*)d_in[wb + 8];
    const float* bl2_um = (const float*)d_in[wb + 9];
    const float* Wr2_um = (const float*)d_in[wb + 10];
    const float* Wl2_mu = (const float*)d_in[wb + 11];
    const float* bl2_mu = (const float*)d_in[wb + 12];
    const float* Wr2_mu = (const float*)d_in[wb + 13];

    float* out = (float*)d_out;

    float* buf = nullptr;
    int*   deg = nullptr;
    int*   ibuf = nullptr;
    cudaGetSymbolAddress((void**)&buf, g_buf);
    cudaGetSymbolAddress((void**)&deg, g_deg);
    cudaGetSymbolAddress((void**)&ibuf, g_ibuf);

    float* movie_x   = buf + OFF_MOVIE_X;
    float* t1t2      = buf + OFF_T1T2;
    float* movie_h   = buf + OFF_MOVIE_H;
    float* movie_tmp = buf + OFF_MOVIE_TMP;
    float* msum      = buf + OFF_MSUM;
    float* movie_o   = buf + OFF_MOVIE_O;
    float* movie_o2  = buf + OFF_MOVIE_O2;
    float* user_h    = buf + OFF_USER_H;
    float* ub        = buf + OFF_UB;
    float* invM      = buf + OFF_INVM;
    float* gateM     = buf + OFF_GATEM;
    float* c1        = buf + OFF_C1;
    float* v1        = buf + OFF_V1;
    float* WT        = buf + OFF_WT;

    int* csrU   = ibuf + IOFF_CSRU;
    int* csrM   = ibuf + IOFF_CSRM;
    int* startU = ibuf + IOFF_STARTU;
    int* startM = ibuf + IOFF_STARTM;
    int* cursU  = ibuf + IOFF_CURSU;
    int* cursM  = ibuf + IOFF_CURSM;
    int* incl   = ibuf + IOFF_INCL;
    int* bsum   = ibuf + IOFF_BSUM;

    const int nbU = (NUc + 1023) / 1024;   // 196
    const int nbM = (NMc + 1023) / 1024;   // 79
    const int gemmM_blocks = NMc / 128;    // 625

    // ---- fork a side stream inside the capture: GEMM chain runs parallel to CSR build
    cudaStream_t s2;
    cudaStreamCreateWithFlags(&s2, cudaStreamNonBlocking);
    cudaEvent_t evFork, evMovieCSR, evSide;
    cudaEventCreateWithFlags(&evFork, cudaEventDisableTiming);
    cudaEventCreateWithFlags(&evMovieCSR, cudaEventDisableTiming);
    cudaEventCreateWithFlags(&evSide, cudaEventDisableTiming);

    cudaEventRecord(evFork, 0);
    cudaStreamWaitEvent(s2, evFork, 0);

    // ======== side stream: weight prep + GEMMs independent of CSR ========
    k_vec<<<1, 128, 0, s2>>>(user_init, Wl1_um, Wr1_mu, bl1_mu, c1, v1);
    k_transp<<<16, dim3(32, 32), 0, s2>>>(Wr2_mu, WT);
    // movie_x = movie_feats @ Wm + bm   (K=512) — hides the whole CSR build
    k_gemm<<<gemmM_blocks, 256, 0, s2>>>(movie_feats, Wm, movie_x, NMc, FDc, Hc,
                                         bm, nullptr, nullptr, nullptr, nullptr, 0);

    // ======== main stream: CSR build ========
    cudaMemsetAsync(deg, 0, sizeof(int) * (NUc + NMc));
    k_deg<<<(Ec + 255) / 256, 256>>>(edge_src, edge_dst, Ec);

    // movie-side scan first (produces gateM/invM needed by side-stream dual GEMM)
    k_scan1<<<nbM, 1024>>>(deg + NUc, incl, bsum, NMc);
    k_scan2<<<1, 256>>>(bsum, nbM);
    k_scan3<<<nbM, 1024>>>(deg + NUc, incl, bsum, startM, cursM, invM, gateM, NMc);
    cudaEventRecord(evMovieCSR, 0);

    // user-side scan + scatter
    k_scan1<<<nbU, 1024>>>(deg, incl, bsum, NUc);
    k_scan2<<<1, 256>>>(bsum, nbU);
    k_scan3<<<nbU, 1024>>>(deg, incl, bsum, startU, cursU, nullptr, nullptr, NUc);
    k_scatter<<<(Ec + 255) / 256, 256>>>(edge_src, edge_dst, cursU, cursM, csrU, csrM, Ec);

    // ======== side stream: remaining GEMMs (dual needs gateM) ========
    cudaStreamWaitEvent(s2, evMovieCSR, 0);
    // dual: t1 = movie_x@Wl1_mu (ldc=256) ; movie_h = relu(movie_x@Wr1_um + bl1_um + gateM*c1)
    k_gemm_dual<<<dim3(gemmM_blocks, 2), 256, 0, s2>>>(movie_x, NMc, Hc,
        Wl1_mu, t1t2, 256, nullptr, nullptr, nullptr, 0,
        Wr1_um, movie_h, Hc, bl1_um, gateM, c1, 1);
    // dual: t2 = movie_h@Wl2_mu (ldc=256, +128) ; movie_tmp = movie_h@Wr2_um
    k_gemm_dual<<<dim3(gemmM_blocks, 2), 256, 0, s2>>>(movie_h, NMc, Hc,
        Wl2_mu, t1t2 + 128, 256, nullptr, nullptr, nullptr, 0,
        Wr2_um, movie_tmp, Hc, nullptr, nullptr, nullptr, 0);
    cudaEventRecord(evSide, s2);

    // ======== join: aggregations need CSR (main) + t1t2/movie_h (side) ========
    cudaStreamWaitEvent(0, evSide, 0);

    k_agg_user<<<(NUc + 7) / 8, 256>>>((const float4*)t1t2, csrU, startU, v1, bl2_mu,
                                       (float4*)user_h, (float4*)ub);
    k_agg_movie<<<(NMc + 7) / 8, 256>>>((const float4*)user_h, csrM, startM,
                                        (float4*)msum);

    // movie_o = invM*(msum @ Wl2_um) + bl2_um + movie_tmp
    k_gemm<<<gemmM_blocks, 256>>>(msum, Wl2_um, movie_o, NMc, Hc, Hc,
                                  bl2_um, invM, movie_tmp, nullptr, nullptr, 0);
    // movie_o2 = movie_o @ Wr2_mu^T
    k_gemm<<<gemmM_blocks, 256>>>(movie_o, WT, movie_o2, NMc, Hc, Hc,
                                  nullptr, nullptr, nullptr, nullptr, nullptr, 0);

    // out[e] = user_h[u]·movie_o2[m] + ub[u]·movie_o[m]
    k_dot2<<<(ELc + 7) / 8, 256>>>((const float4*)user_h, (const float4*)ub,
                                   (const float4*)movie_o, (const float4*)movie_o2,
                                   lbl_user, lbl_movie, out, ELc);
}